// round 6
// baseline (speedup 1.0000x reference)
#include <cuda_runtime.h>
#include <math.h>

#define Hh 256
#define Ww 512
#define HW (Hh*Ww)          // 131072
#define NPB (HW*2)          // 262144 boxes per branch
#define TOTAL (NPB*2)       // 524288
#define TOPKN 4096
#define CAND_MAX 16384
#define SCORE_THR 0.2f
#define NMS_THR 0.15f

// libdevice expf — bit-exact match for XLA's kExp lowering, immune to --use_fast_math remapping
extern "C" __device__ float __nv_expf(float);

// ---------------- device scratch (static, no allocs) ----------------
__device__ unsigned int       g_hist0[65536];         // 256 KB
__device__ int                g_bucket;
__device__ unsigned int       g_cnt;
__device__ unsigned long long g_sel[CAND_MAX];        // candidate score-keys
__device__ float              g_topscore[TOPKN];
__device__ float4             g_standup[TOPKN];
__device__ unsigned long long g_sup[TOPKN*64];        // suppression bitmask (upper triangle words only)

// monotone map: float bits -> unsigned, order-preserving
__device__ __forceinline__ unsigned int mono32(float v) {
    unsigned int u = __float_as_uint(v);
    return (u & 0x80000000u) ? ~u : (u | 0x80000000u);
}

// EXACT XLA logistic: 1 / (1 + __nv_expf(-x)), forced round-to-nearest division
__device__ __forceinline__ float xla_sigmoid(float x) {
    float e = __nv_expf(-x);
    return __fdiv_rn(1.0f, __fadd_rn(1.0f, e));
}

// ---------------- histogram of raw-logit upper-16 bits (no sigmoid!) ----------------
__global__ void k_keys(const float* __restrict__ psm_v, const float* __restrict__ psm_i) {
    int n = blockIdx.x*blockDim.x + threadIdx.x;
    int local = (n < NPB) ? n : n - NPB;
    const float* psm = (n < NPB) ? psm_v : psm_i;
    int cell = local >> 1, a = local & 1;
    float x = __ldg(&psm[a*HW + cell]);
    // sigmoid is strictly monotone: top-4096 by score == top by raw logit (set-wise;
    // exact ordering resolved later on the exact float sigmoid among candidates)
    atomicAdd(&g_hist0[mono32(x) >> 16], 1u);
}

// ---------------- pick 16-bit logit bucket containing the 4096th entry ----------------
__global__ void k_bucket() {
    __shared__ unsigned int csum[1024];
    int t = threadIdx.x;
    unsigned int s = 0;
    #pragma unroll 4
    for (int i = 0; i < 64; i++) s += g_hist0[t*64 + i];
    csum[t] = s;
    __syncthreads();
    if (t == 0) {
        unsigned int k = TOPKN, cum = 0;
        int chunk = 1023;
        for (; chunk > 0; chunk--) {
            if (cum + csum[chunk] >= k) break;
            cum += csum[chunk];
        }
        int B = chunk*64;
        for (int b = 63; b >= 0; b--) {
            unsigned int h = g_hist0[chunk*64 + b];
            if (cum + h >= k) { B = chunk*64 + b; break; }
            cum += h;
        }
        g_bucket = B;
        g_cnt = 0u;
    }
}

// ---------------- compact candidates; exact XLA-matching sigmoid ONLY here (~4.3k) ----------------
__global__ void k_compact(const float* __restrict__ psm_v, const float* __restrict__ psm_i) {
    int n = blockIdx.x*blockDim.x + threadIdx.x;
    int local = (n < NPB) ? n : n - NPB;
    const float* psm = (n < NPB) ? psm_v : psm_i;
    int cell = local >> 1, a = local & 1;
    float x = __ldg(&psm[a*HW + cell]);
    if ((int)(mono32(x) >> 16) >= g_bucket) {
        float s = xla_sigmoid(x);
        float m = (s > SCORE_THR) ? s : -1.0f;
        unsigned long long key = ((unsigned long long)mono32(m) << 32) |
                                 (unsigned long long)(0xFFFFFFFFu - (unsigned int)n); // low index wins ties
        unsigned int p = atomicAdd(&g_cnt, 1u);
        if (p < CAND_MAX) g_sel[p] = key;
    }
}

// ---------------- geometry helpers ----------------
__device__ __forceinline__ void mkcorners(float bx, float by, float bz,
                                          float bh, float bw, float bl, float yaw,
                                          float* X, float* Y, float* Z) {
    const float sx[8] = { .5f, .5f,-.5f,-.5f, .5f, .5f,-.5f,-.5f};
    const float sy[8] = { .5f,-.5f,-.5f, .5f, .5f,-.5f,-.5f, .5f};
    const float sz[8] = {-.5f,-.5f,-.5f,-.5f, .5f, .5f, .5f, .5f};
    float c = cosf(yaw), sn = sinf(yaw);
    #pragma unroll
    for (int k = 0; k < 8; k++) {
        float x = bl*sx[k], y = bw*sy[k], z = bh*sz[k];
        X[k] = x*c - y*sn + bx;
        Y[k] = x*sn + y*c + by;
        Z[k] = z + bz;
    }
}

__device__ __forceinline__ void xform(const float* __restrict__ T,
                                      const float* X, const float* Y, const float* Z,
                                      float* OX, float* OY, float* OZ) {
    float t00=T[0],t01=T[1],t02=T[2],t03=T[3];
    float t10=T[4],t11=T[5],t12=T[6],t13=T[7];
    float t20=T[8],t21=T[9],t22=T[10],t23=T[11];
    #pragma unroll
    for (int k = 0; k < 8; k++) {
        OX[k] = t00*X[k] + t01*Y[k] + t02*Z[k] + t03;
        OY[k] = t10*X[k] + t11*Y[k] + t12*Z[k] + t13;
        OZ[k] = t20*X[k] + t21*Y[k] + t22*Z[k] + t23;
    }
}

// ---------------- rank-select (exact rank by counting) fused with decode ----------------
__global__ void k_select(const float* __restrict__ anchors,
                         const float* __restrict__ rm_v,
                         const float* __restrict__ rm_i,
                         const float* __restrict__ t_proj,
                         const float* __restrict__ t_ego,
                         float* __restrict__ out) {
    __shared__ unsigned long long tile[2048];
    int tid = threadIdx.x;
    int r = blockIdx.x*1024 + tid;
    int C = (int)g_cnt; if (C > CAND_MAX) C = CAND_MAX;
    unsigned long long mykey = (r < C) ? g_sel[r] : 0ull;
    int rank = 0;
    for (int base = 0; base < C; base += 2048) {
        int len = C - base; if (len > 2048) len = 2048;
        __syncthreads();
        for (int i = tid; i < len; i += 1024) tile[i] = g_sel[base + i];
        __syncthreads();
        if (r < C) {
            int i = 0;
            for (; i + 4 <= len; i += 4) {
                rank += (int)(tile[i]   > mykey) + (int)(tile[i+1] > mykey)
                      + (int)(tile[i+2] > mykey) + (int)(tile[i+3] > mykey);
            }
            for (; i < len; i++) rank += (int)(tile[i] > mykey);
        }
    }
    if (r >= C || rank >= TOPKN) return;

    // unpack key -> score + original index
    unsigned int u = (unsigned int)(mykey >> 32);
    unsigned int fu = (u & 0x80000000u) ? (u & 0x7FFFFFFFu) : ~u;
    float score = __uint_as_float(fu);
    int n = (int)(0xFFFFFFFFu - (unsigned int)(mykey & 0xFFFFFFFFull));
    g_topscore[rank] = score;

    bool isI = (n >= NPB);
    int local = isI ? (n - NPB) : n;
    const float* rm = isI ? rm_i : rm_v;
    int cell = local >> 1, a = local & 1;

    float d[7], anc[7];
    #pragma unroll
    for (int j = 0; j < 7; j++) {
        d[j]   = __ldg(&rm[(a*7 + j)*HW + cell]);
        anc[j] = __ldg(&anchors[local*7 + j]);
    }
    float ad = sqrtf(anc[4]*anc[4] + anc[5]*anc[5]);
    float bx = d[0]*ad + anc[0];
    float by = d[1]*ad + anc[1];
    float bz = d[2]*anc[3] + anc[2];
    float bh = expf(d[3])*anc[3];
    float bw = expf(d[4])*anc[4];
    float bl = expf(d[5])*anc[5];
    float byaw = d[6] + anc[6];

    float CX[8], CY[8], CZ[8];
    mkcorners(bx, by, bz, bh, bw, bl, byaw, CX, CY, CZ);

    if (isI) {
        float PX[8], PY[8], PZ[8];
        xform(t_proj, CX, CY, CZ, PX, PY, PZ);
        float mx=0.f, my=0.f, mz=0.f;
        #pragma unroll
        for (int k = 0; k < 8; k++) { mx += PX[k]; my += PY[k]; mz += PZ[k]; }
        mx *= 0.125f; my *= 0.125f; mz *= 0.125f;
        float hh = (PZ[4]+PZ[5]+PZ[6]+PZ[7])*0.25f - (PZ[0]+PZ[1]+PZ[2]+PZ[3])*0.25f;
        const int li0[4] = {0,1,4,5}, li1[4] = {3,2,7,6};
        const int wi0[4] = {0,3,4,7}, wi1[4] = {1,2,5,6};
        float sl = 0.f, sw = 0.f, sumx = 0.f, sumy = 0.f;
        #pragma unroll
        for (int t2 = 0; t2 < 4; t2++) {
            float dx = PX[li0[t2]] - PX[li1[t2]];
            float dy = PY[li0[t2]] - PY[li1[t2]];
            sl += sqrtf(dx*dx + dy*dy);
            sumx += dx; sumy += dy;
        }
        #pragma unroll
        for (int t2 = 0; t2 < 4; t2++) {
            float dx = PX[wi0[t2]] - PX[wi1[t2]];
            float dy = PY[wi0[t2]] - PY[wi1[t2]];
            sw += sqrtf(dx*dx + dy*dy);
        }
        float ll = sl*0.25f, ww = sw*0.25f;
        float yaw2 = atan2f(sumy, sumx);
        mkcorners(mx, my, mz, hh, ww, ll, yaw2, CX, CY, CZ);
    }

    float OX[8], OY[8], OZ[8];
    xform(t_ego, CX, CY, CZ, OX, OY, OZ);

    float mnx = OX[0], mny = OY[0], mxx = OX[0], mxy = OY[0];
    #pragma unroll
    for (int k = 0; k < 8; k++) {
        out[rank*25 + k*3 + 0] = OX[k];
        out[rank*25 + k*3 + 1] = OY[k];
        out[rank*25 + k*3 + 2] = OZ[k];
        mnx = fminf(mnx, OX[k]); mny = fminf(mny, OY[k]);
        mxx = fmaxf(mxx, OX[k]); mxy = fmaxf(mxy, OY[k]);
    }
    g_standup[rank] = make_float4(mnx, mny, mxx, mxy);
}

// ---------------- suppression bitmask: upper-triangle 64x64 tiles, zero-inter reject ----------------
__global__ void k_sup() {
    __shared__ float4 sj[64];
    int bid = blockIdx.x;
    // map linear bid -> (it, jt) with jt >= it over 64 tile-rows
    int it = 0, rem = bid;
    while (rem >= 64 - it) { rem -= 64 - it; it++; }
    int jt = it + rem;
    int t = threadIdx.x;                 // row within i-tile
    sj[t] = g_standup[jt*64 + t];
    __syncthreads();
    int i = it*64 + t;
    float4 bi = g_standup[i];
    float areai = (bi.z - bi.x)*(bi.w - bi.y);
    unsigned long long m = 0ull;
    #pragma unroll 4
    for (int jj = 0; jj < 64; jj++) {
        int j = jt*64 + jj;
        float4 bj = sj[jj];              // broadcast (all threads same address)
        float ltx = fmaxf(bi.x, bj.x), lty = fmaxf(bi.y, bj.y);
        float rbx = fminf(bi.z, bj.z), rby = fminf(bi.w, bj.w);
        float iw = fmaxf(rbx - ltx, 0.f), ih = fmaxf(rby - lty, 0.f);
        float inter = iw*ih;
        if (inter > 0.f && j > i) {      // quick reject: iou==0 exactly when inter==0
            float areaj = (bj.z - bj.x)*(bj.w - bj.y);
            float iou = inter / (areai + areaj - inter + 1e-6f);
            if (iou > NMS_THR) m |= (1ull << jj);
        }
    }
    g_sup[(size_t)i*64 + jt] = m;
}

// ---------------- greedy NMS: 64 threads, triangle-guarded, prefetched diag ----------------
__global__ void k_nms(float* __restrict__ out) {
    __shared__ unsigned long long dbuf[2][64];
    __shared__ unsigned long long cur_s;
    __shared__ int klist[64];
    __shared__ int kcnt_s;
    int t = threadIdx.x;   // word t covers boxes t*64..t*64+63
    unsigned long long acc = 0ull;
    // invalid boxes (score <= thr) start suppressed
    #pragma unroll 4
    for (int b = 0; b < 64; b++) {
        if (!(g_topscore[t*64 + b] > SCORE_THR)) acc |= (1ull << b);
    }
    // prefetch diag of chunk 0 (word 0 of rows 0..63 — tile (0,0), written)
    dbuf[0][t] = g_sup[(size_t)t*64 + 0];
    for (int c = 0; c < 64; c++) {
        if (t == c) cur_s = acc;
        __syncthreads();
        if (t == 0) {
            // preload diag into registers: MLP-batched LDS, then a fully-unrolled
            // CONSTANT-INDEX scan (keeps dg[] in named registers, no local-mem spill)
            unsigned long long dg[64];
            #pragma unroll
            for (int b = 0; b < 64; b++) dg[b] = dbuf[c & 1][b];
            unsigned long long curw = cur_s;
            int kc = 0;
            #pragma unroll
            for (int b = 0; b < 64; b++) {
                if (!((curw >> b) & 1ull)) { klist[kc++] = b; curw |= dg[b]; }
            }
            kcnt_s = kc;
        }
        __syncthreads();
        // prefetch next chunk's diag (independent of NMS state) overlapping row ORs
        if (c < 63) dbuf[(c + 1) & 1][t] = g_sup[((size_t)(c+1)*64 + t)*64 + (c+1)];
        if (t >= c) {   // triangle: words below c were never written (semantically zero)
            int kc = kcnt_s;
            const unsigned long long* base = &g_sup[(size_t)c*64*64 + t];
            for (int p = 0; p < kc; p += 32) {      // 32-deep predicated batches (high MLP)
                unsigned long long r = 0ull;
                #pragma unroll
                for (int q = 0; q < 32; q++) {
                    int idx = p + q;
                    int safe = klist[(idx < kc) ? idx : 0];     // clamped (klist[0] valid when kc>0)
                    unsigned long long v = (idx < kc) ? base[(size_t)safe*64] : 0ull;
                    r |= v;
                }
                acc |= r;
            }
        }
        __syncthreads();
    }
    // write final scores column
    int basebox = t*64;
    #pragma unroll 4
    for (int b = 0; b < 64; b++) {
        float v = ((acc >> b) & 1ull) ? 0.0f : g_topscore[basebox + b];
        out[(basebox + b)*25 + 24] = v;
    }
}

// ---------------- launch ----------------
extern "C" void kernel_launch(void* const* d_in, const int* in_sizes, int n_in,
                              void* d_out, int out_size) {
    (void)in_sizes; (void)n_in; (void)out_size;
    const float* anchors = (const float*)d_in[0];
    const float* psm_v   = (const float*)d_in[1];
    const float* rm_v    = (const float*)d_in[2];
    const float* psm_i   = (const float*)d_in[3];
    const float* rm_i    = (const float*)d_in[4];
    const float* t_proj  = (const float*)d_in[5];
    const float* t_ego   = (const float*)d_in[6];
    float* out = (float*)d_out;

    void* hist_ptr = 0;
    cudaGetSymbolAddress(&hist_ptr, g_hist0);
    cudaMemsetAsync(hist_ptr, 0, 65536*sizeof(unsigned int));

    k_keys<<<TOTAL/256, 256>>>(psm_v, psm_i);
    k_bucket<<<1, 1024>>>();
    k_compact<<<TOTAL/256, 256>>>(psm_v, psm_i);
    k_select<<<CAND_MAX/1024, 1024>>>(anchors, rm_v, rm_i, t_proj, t_ego, out);
    k_sup<<<2080, 64>>>();
    k_nms<<<1, 64>>>(out);
}

// round 16
// speedup vs baseline: 1.3630x; 1.3630x over previous
#include <cuda_runtime.h>
#include <math.h>

#define Hh 256
#define Ww 512
#define HW (Hh*Ww)          // 131072
#define NPB (HW*2)          // 262144 boxes per branch
#define TOTAL (NPB*2)       // 524288
#define TOPKN 4096
#define CAND_MAX 16384
#define SCORE_THR 0.2f
#define NMS_THR 0.15f

// libdevice expf — bit-exact match for XLA's kExp lowering, immune to --use_fast_math remapping
extern "C" __device__ float __nv_expf(float);

// ---------------- device scratch (static, no allocs) ----------------
__device__ unsigned int       g_hist0[65536];         // 256 KB
__device__ int                g_bucket;
__device__ unsigned int       g_cnt;
__device__ unsigned long long g_sel[CAND_MAX];        // candidate score-keys
__device__ float              g_topscore[TOPKN];
__device__ float4             g_standup[TOPKN];
__device__ unsigned long long g_sup[TOPKN*64];        // suppression bitmask (upper triangle words only)

// monotone map: float bits -> unsigned, order-preserving
__device__ __forceinline__ unsigned int mono32(float v) {
    unsigned int u = __float_as_uint(v);
    return (u & 0x80000000u) ? ~u : (u | 0x80000000u);
}

// EXACT XLA logistic: 1 / (1 + __nv_expf(-x)), forced round-to-nearest division
__device__ __forceinline__ float xla_sigmoid(float x) {
    float e = __nv_expf(-x);
    return __fdiv_rn(1.0f, __fadd_rn(1.0f, e));
}

// ---------------- histogram of raw-logit upper-16 bits (float4, memory-linear) ----------------
// Iterate in MEMORY order with 128-bit loads; histogram is order-invariant.
__global__ void k_keys(const float* __restrict__ psm_v, const float* __restrict__ psm_i) {
    int tid = blockIdx.x*blockDim.x + threadIdx.x;          // 0..TOTAL/4-1
    const float4* psm = (tid < 2*HW/4) ? (const float4*)psm_v : (const float4*)psm_i;
    int m4 = (tid < 2*HW/4) ? tid : tid - 2*HW/4;
    float4 x = __ldg(&psm[m4]);
    atomicAdd(&g_hist0[mono32(x.x) >> 16], 1u);
    atomicAdd(&g_hist0[mono32(x.y) >> 16], 1u);
    atomicAdd(&g_hist0[mono32(x.z) >> 16], 1u);
    atomicAdd(&g_hist0[mono32(x.w) >> 16], 1u);
}

// ---------------- pick 16-bit logit bucket containing the 4096th entry ----------------
__global__ void k_bucket() {
    __shared__ unsigned int csum[1024];
    int t = threadIdx.x;
    unsigned int s = 0;
    #pragma unroll 4
    for (int i = 0; i < 64; i++) s += g_hist0[t*64 + i];
    csum[t] = s;
    __syncthreads();
    if (t == 0) {
        unsigned int k = TOPKN, cum = 0;
        int chunk = 1023;
        for (; chunk > 0; chunk--) {
            if (cum + csum[chunk] >= k) break;
            cum += csum[chunk];
        }
        int B = chunk*64;
        for (int b = 63; b >= 0; b--) {
            unsigned int h = g_hist0[chunk*64 + b];
            if (cum + h >= k) { B = chunk*64 + b; break; }
            cum += h;
        }
        g_bucket = B;
        g_cnt = 0u;
    }
}

// ---------------- compact candidates (float4 scan); exact sigmoid ONLY here (~4.3k) ----------------
__global__ void k_compact(const float* __restrict__ psm_v, const float* __restrict__ psm_i) {
    int tid = blockIdx.x*blockDim.x + threadIdx.x;          // 0..TOTAL/4-1
    int branch = (tid < 2*HW/4) ? 0 : 1;
    const float4* psm = branch ? (const float4*)psm_i : (const float4*)psm_v;
    int m4 = tid - branch*(2*HW/4);
    float4 xv = __ldg(&psm[m4]);
    float xs[4] = {xv.x, xv.y, xv.z, xv.w};
    int B = g_bucket;
    #pragma unroll
    for (int k = 0; k < 4; k++) {
        float x = xs[k];
        if ((int)(mono32(x) >> 16) >= B) {
            int m = m4*4 + k;               // linear offset: m = a*HW + cell
            int a = m >> 17;                // HW = 2^17
            int cell = m & (HW - 1);
            int n = branch*NPB + cell*2 + a;    // box index (matches reference ordering)
            float s = xla_sigmoid(x);
            float mm = (s > SCORE_THR) ? s : -1.0f;
            unsigned long long key = ((unsigned long long)mono32(mm) << 32) |
                                     (unsigned long long)(0xFFFFFFFFu - (unsigned int)n); // low index wins ties
            unsigned int p = atomicAdd(&g_cnt, 1u);
            if (p < CAND_MAX) g_sel[p] = key;
        }
    }
}

// ---------------- geometry helpers ----------------
__device__ __forceinline__ void mkcorners(float bx, float by, float bz,
                                          float bh, float bw, float bl, float yaw,
                                          float* X, float* Y, float* Z) {
    const float sx[8] = { .5f, .5f,-.5f,-.5f, .5f, .5f,-.5f,-.5f};
    const float sy[8] = { .5f,-.5f,-.5f, .5f, .5f,-.5f,-.5f, .5f};
    const float sz[8] = {-.5f,-.5f,-.5f,-.5f, .5f, .5f, .5f, .5f};
    float c = cosf(yaw), sn = sinf(yaw);
    #pragma unroll
    for (int k = 0; k < 8; k++) {
        float x = bl*sx[k], y = bw*sy[k], z = bh*sz[k];
        X[k] = x*c - y*sn + bx;
        Y[k] = x*sn + y*c + by;
        Z[k] = z + bz;
    }
}

__device__ __forceinline__ void xform(const float* __restrict__ T,
                                      const float* X, const float* Y, const float* Z,
                                      float* OX, float* OY, float* OZ) {
    float t00=T[0],t01=T[1],t02=T[2],t03=T[3];
    float t10=T[4],t11=T[5],t12=T[6],t13=T[7];
    float t20=T[8],t21=T[9],t22=T[10],t23=T[11];
    #pragma unroll
    for (int k = 0; k < 8; k++) {
        OX[k] = t00*X[k] + t01*Y[k] + t02*Z[k] + t03;
        OY[k] = t10*X[k] + t11*Y[k] + t12*Z[k] + t13;
        OZ[k] = t20*X[k] + t21*Y[k] + t22*Z[k] + t23;
    }
}

// ---------------- rank-select (exact rank by counting) fused with decode ----------------
// 128 blocks x 128 threads: same O(C^2) compares but spread across the whole chip
__global__ void k_select(const float* __restrict__ anchors,
                         const float* __restrict__ rm_v,
                         const float* __restrict__ rm_i,
                         const float* __restrict__ t_proj,
                         const float* __restrict__ t_ego,
                         float* __restrict__ out) {
    __shared__ unsigned long long tile[2048];
    int tid = threadIdx.x;
    int r = blockIdx.x*128 + tid;
    int C = (int)g_cnt; if (C > CAND_MAX) C = CAND_MAX;
    unsigned long long mykey = (r < C) ? g_sel[r] : 0ull;
    int rank = 0;
    for (int base = 0; base < C; base += 2048) {
        int len = C - base; if (len > 2048) len = 2048;
        __syncthreads();
        for (int i = tid; i < len; i += 128) tile[i] = g_sel[base + i];
        __syncthreads();
        if (r < C) {
            int i = 0;
            for (; i + 4 <= len; i += 4) {
                rank += (int)(tile[i]   > mykey) + (int)(tile[i+1] > mykey)
                      + (int)(tile[i+2] > mykey) + (int)(tile[i+3] > mykey);
            }
            for (; i < len; i++) rank += (int)(tile[i] > mykey);
        }
    }
    if (r >= C || rank >= TOPKN) return;

    // unpack key -> score + original index
    unsigned int u = (unsigned int)(mykey >> 32);
    unsigned int fu = (u & 0x80000000u) ? (u & 0x7FFFFFFFu) : ~u;
    float score = __uint_as_float(fu);
    int n = (int)(0xFFFFFFFFu - (unsigned int)(mykey & 0xFFFFFFFFull));
    g_topscore[rank] = score;

    bool isI = (n >= NPB);
    int local = isI ? (n - NPB) : n;
    const float* rm = isI ? rm_i : rm_v;
    int cell = local >> 1, a = local & 1;

    float d[7], anc[7];
    #pragma unroll
    for (int j = 0; j < 7; j++) {
        d[j]   = __ldg(&rm[(a*7 + j)*HW + cell]);
        anc[j] = __ldg(&anchors[local*7 + j]);
    }
    float ad = sqrtf(anc[4]*anc[4] + anc[5]*anc[5]);
    float bx = d[0]*ad + anc[0];
    float by = d[1]*ad + anc[1];
    float bz = d[2]*anc[3] + anc[2];
    float bh = expf(d[3])*anc[3];
    float bw = expf(d[4])*anc[4];
    float bl = expf(d[5])*anc[5];
    float byaw = d[6] + anc[6];

    float CX[8], CY[8], CZ[8];
    mkcorners(bx, by, bz, bh, bw, bl, byaw, CX, CY, CZ);

    if (isI) {
        float PX[8], PY[8], PZ[8];
        xform(t_proj, CX, CY, CZ, PX, PY, PZ);
        float mx=0.f, my=0.f, mz=0.f;
        #pragma unroll
        for (int k = 0; k < 8; k++) { mx += PX[k]; my += PY[k]; mz += PZ[k]; }
        mx *= 0.125f; my *= 0.125f; mz *= 0.125f;
        float hh = (PZ[4]+PZ[5]+PZ[6]+PZ[7])*0.25f - (PZ[0]+PZ[1]+PZ[2]+PZ[3])*0.25f;
        const int li0[4] = {0,1,4,5}, li1[4] = {3,2,7,6};
        const int wi0[4] = {0,3,4,7}, wi1[4] = {1,2,5,6};
        float sl = 0.f, sw = 0.f, sumx = 0.f, sumy = 0.f;
        #pragma unroll
        for (int t2 = 0; t2 < 4; t2++) {
            float dx = PX[li0[t2]] - PX[li1[t2]];
            float dy = PY[li0[t2]] - PY[li1[t2]];
            sl += sqrtf(dx*dx + dy*dy);
            sumx += dx; sumy += dy;
        }
        #pragma unroll
        for (int t2 = 0; t2 < 4; t2++) {
            float dx = PX[wi0[t2]] - PX[wi1[t2]];
            float dy = PY[wi0[t2]] - PY[wi1[t2]];
            sw += sqrtf(dx*dx + dy*dy);
        }
        float ll = sl*0.25f, ww = sw*0.25f;
        float yaw2 = atan2f(sumy, sumx);
        mkcorners(mx, my, mz, hh, ww, ll, yaw2, CX, CY, CZ);
    }

    float OX[8], OY[8], OZ[8];
    xform(t_ego, CX, CY, CZ, OX, OY, OZ);

    float mnx = OX[0], mny = OY[0], mxx = OX[0], mxy = OY[0];
    #pragma unroll
    for (int k = 0; k < 8; k++) {
        out[rank*25 + k*3 + 0] = OX[k];
        out[rank*25 + k*3 + 1] = OY[k];
        out[rank*25 + k*3 + 2] = OZ[k];
        mnx = fminf(mnx, OX[k]); mny = fminf(mny, OY[k]);
        mxx = fmaxf(mxx, OX[k]); mxy = fmaxf(mxy, OY[k]);
    }
    g_standup[rank] = make_float4(mnx, mny, mxx, mxy);
}

// ---------------- suppression bitmask: upper-triangle 64x64 tiles, zero-inter reject ----------------
__global__ void k_sup() {
    __shared__ float4 sj[64];
    int bid = blockIdx.x;
    int it = 0, rem = bid;
    while (rem >= 64 - it) { rem -= 64 - it; it++; }
    int jt = it + rem;
    int t = threadIdx.x;
    sj[t] = g_standup[jt*64 + t];
    __syncthreads();
    int i = it*64 + t;
    float4 bi = g_standup[i];
    float areai = (bi.z - bi.x)*(bi.w - bi.y);
    unsigned long long m = 0ull;
    #pragma unroll 4
    for (int jj = 0; jj < 64; jj++) {
        int j = jt*64 + jj;
        float4 bj = sj[jj];
        float ltx = fmaxf(bi.x, bj.x), lty = fmaxf(bi.y, bj.y);
        float rbx = fminf(bi.z, bj.z), rby = fminf(bi.w, bj.w);
        float iw = fmaxf(rbx - ltx, 0.f), ih = fmaxf(rby - lty, 0.f);
        float inter = iw*ih;
        if (inter > 0.f && j > i) {
            float areaj = (bj.z - bj.x)*(bj.w - bj.y);
            float iou = inter / (areai + areaj - inter + 1e-6f);
            if (iou > NMS_THR) m |= (1ull << jj);
        }
    }
    g_sup[(size_t)i*64 + jt] = m;
}

// ---------------- greedy NMS: 256 threads = 4 subgroups x 64 words ----------------
// Subgroup g accumulates a partial suppressed-mask over its quarter of kept rows;
// the serial scan only ever needs ONE fully-merged word (word c), OR'd from 4 partials.
__global__ void k_nms(float* __restrict__ out) {
    __shared__ unsigned long long dbuf[2][64];
    __shared__ unsigned long long curparts[4];
    __shared__ unsigned long long fin[4][64];
    __shared__ int klist[64];
    __shared__ int kcnt_s;
    int tid = threadIdx.x;   // 0..255
    int t = tid & 63;        // word index (boxes t*64..t*64+63)
    int g = tid >> 6;        // subgroup 0..3
    unsigned long long acc = 0ull;
    // invalid boxes (score <= thr) start suppressed — held only in subgroup 0's partial
    if (g == 0) {
        #pragma unroll 4
        for (int b = 0; b < 64; b++) {
            if (!(g_topscore[t*64 + b] > SCORE_THR)) acc |= (1ull << b);
        }
        // prefetch diag of chunk 0
        dbuf[0][t] = g_sup[(size_t)t*64 + 0];
    }
    __syncthreads();
    for (int c = 0; c < 64; c++) {
        if (t == c) curparts[g] = acc;
        __syncthreads();
        if (tid == 0) {
            unsigned long long cur = curparts[0] | curparts[1] | curparts[2] | curparts[3];
            // preload diag into registers, then fully-unrolled CONSTANT-INDEX scan
            unsigned long long dg[64];
            #pragma unroll
            for (int b = 0; b < 64; b++) dg[b] = dbuf[c & 1][b];
            unsigned long long curw = cur;
            int kc = 0;
            #pragma unroll
            for (int b = 0; b < 64; b++) {
                if (!((curw >> b) & 1ull)) { klist[kc++] = b; curw |= dg[b]; }
            }
            kcnt_s = kc;
        }
        __syncthreads();
        // prefetch next chunk's diag (independent of NMS state) overlapping row ORs
        if (g == 0 && c < 63) dbuf[(c + 1) & 1][t] = g_sup[((size_t)(c+1)*64 + t)*64 + (c+1)];
        if (t >= c) {   // triangle: words below c were never written (semantically zero)
            int kc = kcnt_s;
            const unsigned long long* base = &g_sup[(size_t)c*64*64 + t];
            for (int p = g; p < kc; p += 32) {      // subgroup-strided, 8-deep batches
                unsigned long long r = 0ull;
                #pragma unroll
                for (int q = 0; q < 8; q++) {
                    int idx = p + q*4;
                    int safe = klist[(idx < kc) ? idx : 0];
                    unsigned long long v = (idx < kc) ? base[(size_t)safe*64] : 0ull;
                    r |= v;
                }
                acc |= r;
            }
        }
        __syncthreads();
    }
    // merge 4 partials and write final scores column
    fin[g][t] = acc;
    __syncthreads();
    if (g == 0) {
        unsigned long long a = fin[0][t] | fin[1][t] | fin[2][t] | fin[3][t];
        int basebox = t*64;
        #pragma unroll 4
        for (int b = 0; b < 64; b++) {
            float v = ((a >> b) & 1ull) ? 0.0f : g_topscore[basebox + b];
            out[(basebox + b)*25 + 24] = v;
        }
    }
}

// ---------------- launch ----------------
extern "C" void kernel_launch(void* const* d_in, const int* in_sizes, int n_in,
                              void* d_out, int out_size) {
    (void)in_sizes; (void)n_in; (void)out_size;
    const float* anchors = (const float*)d_in[0];
    const float* psm_v   = (const float*)d_in[1];
    const float* rm_v    = (const float*)d_in[2];
    const float* psm_i   = (const float*)d_in[3];
    const float* rm_i    = (const float*)d_in[4];
    const float* t_proj  = (const float*)d_in[5];
    const float* t_ego   = (const float*)d_in[6];
    float* out = (float*)d_out;

    void* hist_ptr = 0;
    cudaGetSymbolAddress(&hist_ptr, g_hist0);
    cudaMemsetAsync(hist_ptr, 0, 65536*sizeof(unsigned int));

    k_keys<<<TOTAL/4/256, 256>>>(psm_v, psm_i);
    k_bucket<<<1, 1024>>>();
    k_compact<<<TOTAL/4/256, 256>>>(psm_v, psm_i);
    k_select<<<CAND_MAX/128, 128>>>(anchors, rm_v, rm_i, t_proj, t_ego, out);
    k_sup<<<2080, 64>>>();
    k_nms<<<1, 256>>>(out);
}

// round 17
// speedup vs baseline: 1.3854x; 1.0164x over previous
#include <cuda_runtime.h>
#include <math.h>

#define Hh 256
#define Ww 512
#define HW (Hh*Ww)          // 131072
#define NPB (HW*2)          // 262144 boxes per branch
#define TOTAL (NPB*2)       // 524288
#define TOPKN 4096
#define CAND_MAX 16384
#define SCORE_THR 0.2f
#define NMS_THR 0.15f

// spatial bin grid for suppression (12 m cells; non-neighbor cells cannot hold overlapping pairs)
#define CELLX 24
#define CELLY 14
#define NCELL (CELLX*CELLY)
#define CELL_CAP 256
#define CELL_INV (1.0f/12.0f)
#define GX0 (-144.0f)
#define GY0 (-84.0f)

// libdevice expf — bit-exact match for XLA's kExp lowering, immune to --use_fast_math remapping
extern "C" __device__ float __nv_expf(float);

// ---------------- device scratch (static, no allocs) ----------------
__device__ unsigned int       g_hist0[65536];         // 256 KB
__device__ int                g_bucket;
__device__ unsigned int       g_cnt;
__device__ unsigned long long g_sel[CAND_MAX];        // candidate score-keys
__device__ float              g_topscore[TOPKN];
__device__ float4             g_standup[TOPKN];
__device__ unsigned long long g_sup[TOPKN*64];        // suppression bitmask (zeroed; sparse atomicOr)
__device__ unsigned int       g_cellcnt[NCELL];
__device__ int                g_celllist[NCELL*CELL_CAP];

// monotone map: float bits -> unsigned, order-preserving
__device__ __forceinline__ unsigned int mono32(float v) {
    unsigned int u = __float_as_uint(v);
    return (u & 0x80000000u) ? ~u : (u | 0x80000000u);
}

// EXACT XLA logistic: 1 / (1 + __nv_expf(-x)), forced round-to-nearest division
__device__ __forceinline__ float xla_sigmoid(float x) {
    float e = __nv_expf(-x);
    return __fdiv_rn(1.0f, __fadd_rn(1.0f, e));
}

__device__ __forceinline__ void box_cell(const float4& b, int& cx, int& cy) {
    float cxf = (b.x + b.z)*0.5f;
    float cyf = (b.y + b.w)*0.5f;
    cx = (int)floorf((cxf - GX0)*CELL_INV);
    cy = (int)floorf((cyf - GY0)*CELL_INV);
    cx = cx < 0 ? 0 : (cx > CELLX-1 ? CELLX-1 : cx);
    cy = cy < 0 ? 0 : (cy > CELLY-1 ? CELLY-1 : cy);
}

// ---------------- histogram of raw-logit upper-16 bits (float4, memory-linear) ----------------
__global__ void k_keys(const float* __restrict__ psm_v, const float* __restrict__ psm_i) {
    int tid = blockIdx.x*blockDim.x + threadIdx.x;          // 0..TOTAL/4-1
    const float4* psm = (tid < 2*HW/4) ? (const float4*)psm_v : (const float4*)psm_i;
    int m4 = (tid < 2*HW/4) ? tid : tid - 2*HW/4;
    float4 x = __ldg(&psm[m4]);
    atomicAdd(&g_hist0[mono32(x.x) >> 16], 1u);
    atomicAdd(&g_hist0[mono32(x.y) >> 16], 1u);
    atomicAdd(&g_hist0[mono32(x.z) >> 16], 1u);
    atomicAdd(&g_hist0[mono32(x.w) >> 16], 1u);
}

// ---------------- pick 16-bit logit bucket containing the 4096th entry ----------------
__global__ void k_bucket() {
    __shared__ unsigned int csum[1024];
    int t = threadIdx.x;
    unsigned int s = 0;
    #pragma unroll 4
    for (int i = 0; i < 64; i++) s += g_hist0[t*64 + i];
    csum[t] = s;
    __syncthreads();
    if (t == 0) {
        unsigned int k = TOPKN, cum = 0;
        int chunk = 1023;
        for (; chunk > 0; chunk--) {
            if (cum + csum[chunk] >= k) break;
            cum += csum[chunk];
        }
        int B = chunk*64;
        for (int b = 63; b >= 0; b--) {
            unsigned int h = g_hist0[chunk*64 + b];
            if (cum + h >= k) { B = chunk*64 + b; break; }
            cum += h;
        }
        g_bucket = B;
        g_cnt = 0u;
    }
}

// ---------------- compact candidates (float4 scan); exact sigmoid ONLY here (~4.3k) ----------------
__global__ void k_compact(const float* __restrict__ psm_v, const float* __restrict__ psm_i) {
    int tid = blockIdx.x*blockDim.x + threadIdx.x;          // 0..TOTAL/4-1
    int branch = (tid < 2*HW/4) ? 0 : 1;
    const float4* psm = branch ? (const float4*)psm_i : (const float4*)psm_v;
    int m4 = tid - branch*(2*HW/4);
    float4 xv = __ldg(&psm[m4]);
    float xs[4] = {xv.x, xv.y, xv.z, xv.w};
    int B = g_bucket;
    #pragma unroll
    for (int k = 0; k < 4; k++) {
        float x = xs[k];
        if ((int)(mono32(x) >> 16) >= B) {
            int m = m4*4 + k;               // linear offset: m = a*HW + cell
            int a = m >> 17;                // HW = 2^17
            int cell = m & (HW - 1);
            int n = branch*NPB + cell*2 + a;    // box index (matches reference ordering)
            float s = xla_sigmoid(x);
            float mm = (s > SCORE_THR) ? s : -1.0f;
            unsigned long long key = ((unsigned long long)mono32(mm) << 32) |
                                     (unsigned long long)(0xFFFFFFFFu - (unsigned int)n); // low index wins ties
            unsigned int p = atomicAdd(&g_cnt, 1u);
            if (p < CAND_MAX) g_sel[p] = key;
        }
    }
}

// ---------------- geometry helpers ----------------
__device__ __forceinline__ void mkcorners(float bx, float by, float bz,
                                          float bh, float bw, float bl, float yaw,
                                          float* X, float* Y, float* Z) {
    const float sx[8] = { .5f, .5f,-.5f,-.5f, .5f, .5f,-.5f,-.5f};
    const float sy[8] = { .5f,-.5f,-.5f, .5f, .5f,-.5f,-.5f, .5f};
    const float sz[8] = {-.5f,-.5f,-.5f,-.5f, .5f, .5f, .5f, .5f};
    float c = cosf(yaw), sn = sinf(yaw);
    #pragma unroll
    for (int k = 0; k < 8; k++) {
        float x = bl*sx[k], y = bw*sy[k], z = bh*sz[k];
        X[k] = x*c - y*sn + bx;
        Y[k] = x*sn + y*c + by;
        Z[k] = z + bz;
    }
}

__device__ __forceinline__ void xform(const float* __restrict__ T,
                                      const float* X, const float* Y, const float* Z,
                                      float* OX, float* OY, float* OZ) {
    float t00=T[0],t01=T[1],t02=T[2],t03=T[3];
    float t10=T[4],t11=T[5],t12=T[6],t13=T[7];
    float t20=T[8],t21=T[9],t22=T[10],t23=T[11];
    #pragma unroll
    for (int k = 0; k < 8; k++) {
        OX[k] = t00*X[k] + t01*Y[k] + t02*Z[k] + t03;
        OY[k] = t10*X[k] + t11*Y[k] + t12*Z[k] + t13;
        OZ[k] = t20*X[k] + t21*Y[k] + t22*Z[k] + t23;
    }
}

// ---------------- rank-select fused with decode: 4 threads cooperate per candidate ----------------
// 128 blocks x 512 threads; block handles 128 candidates; rank partials merged via shfl.
__global__ void k_select(const float* __restrict__ anchors,
                         const float* __restrict__ rm_v,
                         const float* __restrict__ rm_i,
                         const float* __restrict__ t_proj,
                         const float* __restrict__ t_ego,
                         float* __restrict__ out) {
    __shared__ unsigned long long tile[2048];
    int tid = threadIdx.x;          // 0..511
    int sub = tid & 3;              // 0..3 : quarter of the scan
    int r = blockIdx.x*128 + (tid >> 2);
    int C = (int)g_cnt; if (C > CAND_MAX) C = CAND_MAX;
    unsigned long long mykey = (r < C) ? g_sel[r] : 0ull;
    int rank = 0;
    for (int base = 0; base < C; base += 2048) {
        int len = C - base; if (len > 2048) len = 2048;
        __syncthreads();
        for (int i = tid; i < len; i += 512) tile[i] = g_sel[base + i];
        __syncthreads();
        if (r < C) {
            int i = sub;
            for (; i + 12 < len; i += 16) {
                rank += (int)(tile[i]    > mykey) + (int)(tile[i+4]  > mykey)
                      + (int)(tile[i+8]  > mykey) + (int)(tile[i+12] > mykey);
            }
            for (; i < len; i += 4) rank += (int)(tile[i] > mykey);
        }
    }
    // combine 4 partial ranks (lane groups are nibbles: xor 1, xor 2 stay in-group)
    rank += __shfl_xor_sync(0xffffffffu, rank, 1);
    rank += __shfl_xor_sync(0xffffffffu, rank, 2);
    if (sub != 0 || r >= C || rank >= TOPKN) return;

    // unpack key -> score + original index
    unsigned int u = (unsigned int)(mykey >> 32);
    unsigned int fu = (u & 0x80000000u) ? (u & 0x7FFFFFFFu) : ~u;
    float score = __uint_as_float(fu);
    int n = (int)(0xFFFFFFFFu - (unsigned int)(mykey & 0xFFFFFFFFull));
    g_topscore[rank] = score;

    bool isI = (n >= NPB);
    int local = isI ? (n - NPB) : n;
    const float* rm = isI ? rm_i : rm_v;
    int cell = local >> 1, a = local & 1;

    float d[7], anc[7];
    #pragma unroll
    for (int j = 0; j < 7; j++) {
        d[j]   = __ldg(&rm[(a*7 + j)*HW + cell]);
        anc[j] = __ldg(&anchors[local*7 + j]);
    }
    float ad = sqrtf(anc[4]*anc[4] + anc[5]*anc[5]);
    float bx = d[0]*ad + anc[0];
    float by = d[1]*ad + anc[1];
    float bz = d[2]*anc[3] + anc[2];
    float bh = expf(d[3])*anc[3];
    float bw = expf(d[4])*anc[4];
    float bl = expf(d[5])*anc[5];
    float byaw = d[6] + anc[6];

    float CX[8], CY[8], CZ[8];
    mkcorners(bx, by, bz, bh, bw, bl, byaw, CX, CY, CZ);

    if (isI) {
        float PX[8], PY[8], PZ[8];
        xform(t_proj, CX, CY, CZ, PX, PY, PZ);
        float mx=0.f, my=0.f, mz=0.f;
        #pragma unroll
        for (int k = 0; k < 8; k++) { mx += PX[k]; my += PY[k]; mz += PZ[k]; }
        mx *= 0.125f; my *= 0.125f; mz *= 0.125f;
        float hh = (PZ[4]+PZ[5]+PZ[6]+PZ[7])*0.25f - (PZ[0]+PZ[1]+PZ[2]+PZ[3])*0.25f;
        const int li0[4] = {0,1,4,5}, li1[4] = {3,2,7,6};
        const int wi0[4] = {0,3,4,7}, wi1[4] = {1,2,5,6};
        float sl = 0.f, sw = 0.f, sumx = 0.f, sumy = 0.f;
        #pragma unroll
        for (int t2 = 0; t2 < 4; t2++) {
            float dx = PX[li0[t2]] - PX[li1[t2]];
            float dy = PY[li0[t2]] - PY[li1[t2]];
            sl += sqrtf(dx*dx + dy*dy);
            sumx += dx; sumy += dy;
        }
        #pragma unroll
        for (int t2 = 0; t2 < 4; t2++) {
            float dx = PX[wi0[t2]] - PX[wi1[t2]];
            float dy = PY[wi0[t2]] - PY[wi1[t2]];
            sw += sqrtf(dx*dx + dy*dy);
        }
        float ll = sl*0.25f, ww = sw*0.25f;
        float yaw2 = atan2f(sumy, sumx);
        mkcorners(mx, my, mz, hh, ww, ll, yaw2, CX, CY, CZ);
    }

    float OX[8], OY[8], OZ[8];
    xform(t_ego, CX, CY, CZ, OX, OY, OZ);

    float mnx = OX[0], mny = OY[0], mxx = OX[0], mxy = OY[0];
    #pragma unroll
    for (int k = 0; k < 8; k++) {
        out[rank*25 + k*3 + 0] = OX[k];
        out[rank*25 + k*3 + 1] = OY[k];
        out[rank*25 + k*3 + 2] = OZ[k];
        mnx = fminf(mnx, OX[k]); mny = fminf(mny, OY[k]);
        mxx = fmaxf(mxx, OX[k]); mxy = fmaxf(mxy, OY[k]);
    }
    g_standup[rank] = make_float4(mnx, mny, mxx, mxy);
}

// ---------------- bin boxes into 12 m cells ----------------
__global__ void k_bin() {
    int i = blockIdx.x*blockDim.x + threadIdx.x;
    if (i >= TOPKN) return;
    float4 b = g_standup[i];
    int cx, cy;
    box_cell(b, cx, cy);
    int c = cy*CELLX + cx;
    unsigned int p = atomicAdd(&g_cellcnt[c], 1u);
    if (p < CELL_CAP) g_celllist[c*CELL_CAP + p] = i;
}

// ---------------- suppression: warp per box, 3x3 neighbor cells only (~225k pairs) ----------------
__global__ void k_sup() {
    int gw = (blockIdx.x*blockDim.x + threadIdx.x) >> 5;   // global warp = box index
    int lane = threadIdx.x & 31;
    if (gw >= TOPKN) return;
    int i = gw;
    float4 bi = g_standup[i];
    float areai = (bi.z - bi.x)*(bi.w - bi.y);
    int cx, cy;
    box_cell(bi, cx, cy);
    for (int dy = -1; dy <= 1; dy++) {
        int cy2 = cy + dy;
        if (cy2 < 0 || cy2 >= CELLY) continue;
        for (int dx = -1; dx <= 1; dx++) {
            int cx2 = cx + dx;
            if (cx2 < 0 || cx2 >= CELLX) continue;
            int c = cy2*CELLX + cx2;
            int cnt = (int)g_cellcnt[c];
            if (cnt > CELL_CAP) cnt = CELL_CAP;
            for (int idx = lane; idx < cnt; idx += 32) {
                int j = g_celllist[c*CELL_CAP + idx];
                if (j <= i) continue;
                float4 bj = __ldg(&g_standup[j]);
                float ltx = fmaxf(bi.x, bj.x), lty = fmaxf(bi.y, bj.y);
                float rbx = fminf(bi.z, bj.z), rby = fminf(bi.w, bj.w);
                float iw = fmaxf(rbx - ltx, 0.f), ih = fmaxf(rby - lty, 0.f);
                float inter = iw*ih;
                if (inter > 0.f) {
                    float areaj = (bj.z - bj.x)*(bj.w - bj.y);
                    float iou = inter / (areai + areaj - inter + 1e-6f);
                    if (iou > NMS_THR)
                        atomicOr(&g_sup[(size_t)i*64 + (j >> 6)], 1ull << (j & 63));
                }
            }
        }
    }
}

// ---------------- greedy NMS: 256 threads = 4 subgroups x 64 words ----------------
__global__ void k_nms(float* __restrict__ out) {
    __shared__ unsigned long long dbuf[2][64];
    __shared__ unsigned long long curparts[4];
    __shared__ unsigned long long fin[4][64];
    __shared__ int klist[64];
    __shared__ int kcnt_s;
    int tid = threadIdx.x;   // 0..255
    int t = tid & 63;        // word index (boxes t*64..t*64+63)
    int g = tid >> 6;        // subgroup 0..3
    unsigned long long acc = 0ull;
    // invalid boxes (score <= thr) start suppressed — held only in subgroup 0's partial
    if (g == 0) {
        #pragma unroll 4
        for (int b = 0; b < 64; b++) {
            if (!(g_topscore[t*64 + b] > SCORE_THR)) acc |= (1ull << b);
        }
        // prefetch diag of chunk 0
        dbuf[0][t] = g_sup[(size_t)t*64 + 0];
    }
    __syncthreads();
    for (int c = 0; c < 64; c++) {
        if (t == c) curparts[g] = acc;
        __syncthreads();
        if (tid == 0) {
            unsigned long long cur = curparts[0] | curparts[1] | curparts[2] | curparts[3];
            unsigned long long dg[64];
            #pragma unroll
            for (int b = 0; b < 64; b++) dg[b] = dbuf[c & 1][b];
            unsigned long long curw = cur;
            int kc = 0;
            #pragma unroll
            for (int b = 0; b < 64; b++) {
                if (!((curw >> b) & 1ull)) { klist[kc++] = b; curw |= dg[b]; }
            }
            kcnt_s = kc;
        }
        __syncthreads();
        if (g == 0 && c < 63) dbuf[(c + 1) & 1][t] = g_sup[((size_t)(c+1)*64 + t)*64 + (c+1)];
        if (t >= c) {   // rows in chunk c have bits only for j > i >= c*64 → words >= c
            int kc = kcnt_s;
            const unsigned long long* base = &g_sup[(size_t)c*64*64 + t];
            for (int p = g; p < kc; p += 32) {
                unsigned long long r = 0ull;
                #pragma unroll
                for (int q = 0; q < 8; q++) {
                    int idx = p + q*4;
                    int safe = klist[(idx < kc) ? idx : 0];
                    unsigned long long v = (idx < kc) ? base[(size_t)safe*64] : 0ull;
                    r |= v;
                }
                acc |= r;
            }
        }
        __syncthreads();
    }
    fin[g][t] = acc;
    __syncthreads();
    if (g == 0) {
        unsigned long long a = fin[0][t] | fin[1][t] | fin[2][t] | fin[3][t];
        int basebox = t*64;
        #pragma unroll 4
        for (int b = 0; b < 64; b++) {
            float v = ((a >> b) & 1ull) ? 0.0f : g_topscore[basebox + b];
            out[(basebox + b)*25 + 24] = v;
        }
    }
}

// ---------------- launch ----------------
extern "C" void kernel_launch(void* const* d_in, const int* in_sizes, int n_in,
                              void* d_out, int out_size) {
    (void)in_sizes; (void)n_in; (void)out_size;
    const float* anchors = (const float*)d_in[0];
    const float* psm_v   = (const float*)d_in[1];
    const float* rm_v    = (const float*)d_in[2];
    const float* psm_i   = (const float*)d_in[3];
    const float* rm_i    = (const float*)d_in[4];
    const float* t_proj  = (const float*)d_in[5];
    const float* t_ego   = (const float*)d_in[6];
    float* out = (float*)d_out;

    void* p = 0;
    cudaGetSymbolAddress(&p, g_hist0);
    cudaMemsetAsync(p, 0, 65536*sizeof(unsigned int));
    cudaGetSymbolAddress(&p, g_sup);
    cudaMemsetAsync(p, 0, (size_t)TOPKN*64*sizeof(unsigned long long));
    cudaGetSymbolAddress(&p, g_cellcnt);
    cudaMemsetAsync(p, 0, NCELL*sizeof(unsigned int));

    k_keys<<<TOTAL/4/256, 256>>>(psm_v, psm_i);
    k_bucket<<<1, 1024>>>();
    k_compact<<<TOTAL/4/256, 256>>>(psm_v, psm_i);
    k_select<<<CAND_MAX/128, 512>>>(anchors, rm_v, rm_i, t_proj, t_ego, out);
    k_bin<<<TOPKN/256, 256>>>();
    k_sup<<<TOPKN/8, 256>>>();     // 8 warps/block, warp per box
    k_nms<<<1, 256>>>(out);
}